// round 5
// baseline (speedup 1.0000x reference)
#include <cuda_runtime.h>
#include <cuda_bf16.h>

// Shapes fixed by the problem: N=4, Cin=4, Cout=4, K=5, H=W=128.
#define PN    4
#define PCIN  4
#define PCOUT 4
#define PK    5
#define PH    128
#define PW    128
#define PKK   (PK*PK)        // 25
#define PCH   (PCOUT*PKK)    // 100
#define PHW   (PH*PW)        // 16384

#define LOG2E 1.4426950408889634f

// Block: 256 threads = 2 output rows of one (n, c) image.
// Shared tile holds lb * log2e for all 4 cin, 6 rows (2 + 4 halo),
// 132 cols (128 + 4 halo). Halo = -1e30*log2e so out-of-bounds taps give
// ex2(-huge) == 0 -> branch-free boundary handling. lk addresses for those
// taps are clamped to stay legal; their value is irrelevant (term is 0).
#define TR 6
#define TW 132

__device__ __forceinline__ float ex2_approx(float x) {
    float r;
    asm("ex2.approx.ftz.f32 %0, %1;" : "=f"(r) : "f"(x));
    return r;
}

__global__ __launch_bounds__(256, 3) void propagate_belief_kernel(
    const float* __restrict__ lb,   // (N, Cin, H, W)
    const float* __restrict__ lk,   // (N, Cin, Cout*KK, H, W)
    float* __restrict__ out)        // (N, Cout, H, W)
{
    __shared__ float tile[PCIN][TR][TW];

    const int tid = threadIdx.x;
    const int b   = blockIdx.x;          // b = ((n*PCOUT + c)*64 + y0/2)
    const int y0  = (b & 63) * 2;
    const int c   = (b >> 6) & (PCOUT - 1);
    const int n   = b >> 8;

    // ---- stage lb tile, pre-scaled by log2e (with -1e30 halo) ----
    const float* lbn = lb + (size_t)n * PCIN * PHW;
    #pragma unroll 4
    for (int i = tid; i < PCIN * TR * TW; i += 256) {
        int col = i % TW;
        int rr  = (i / TW) % TR;
        int cin = i / (TW * TR);
        int sy  = y0 - 2 + rr;
        int sx  = col - 2;
        float v = -1e30f;
        if ((unsigned)sy < (unsigned)PH && (unsigned)sx < (unsigned)PW)
            v = lbn[cin * PHW + sy * PW + sx];
        tile[cin][rr][col] = v * LOG2E;
    }
    __syncthreads();

    // ---- per-thread output pixel ----
    const int x      = tid & (PW - 1);
    const int ylocal = tid >> 7;          // 0 or 1
    const int y      = y0 + ylocal;

    // Hoisted clamps; combined per-tap offset within one lk (cin,c) slice:
    //   off[ky*5+kx] = (ky*5+kx)*PHW + clamp(y+2-ky)*PW + clamp(x+2-kx)
    int off[PKK];
    int xcol[PK];
    #pragma unroll
    for (int kx = 0; kx < PK; ++kx)
        xcol[kx] = x + 4 - kx;
    #pragma unroll
    for (int ky = 0; ky < PK; ++ky) {
        int sy      = y + 2 - ky;
        int rowbase = min(max(sy, 0), PH - 1) * PW;
        #pragma unroll
        for (int kx = 0; kx < PK; ++kx) {
            int sx = x + 2 - kx;
            off[ky * PK + kx] = (ky * PK + kx) * PHW + rowbase
                              + min(max(sx, 0), PW - 1);
        }
    }

    float sum = 0.0f;

    #pragma unroll
    for (int cin = 0; cin < PCIN; ++cin) {
        const float* lkp = lk +
            (size_t)((n * PCIN + cin) * PCH + c * PKK) * PHW;

        // Batch ALL 25 independent global loads for this cin before any
        // consumer: 25 x 128B in flight per warp -> HBM latency fully hidden.
        float kv[PKK];
        #pragma unroll
        for (int j = 0; j < PKK; ++j)
            kv[j] = __ldg(lkp + off[j]);

        // Each tap: one FFMA + one MUFU.EX2 (+ FADD accumulate).
        #pragma unroll
        for (int ky = 0; ky < PK; ++ky) {
            int rr = ylocal + 4 - ky;
            #pragma unroll
            for (int kx = 0; kx < PK; ++kx)
                sum += ex2_approx(
                    __fmaf_rn(kv[ky * PK + kx], LOG2E, tile[cin][rr][xcol[kx]]));
        }
    }

    out[((n * PCOUT + c) * PH + y) * PW + x] = __logf(sum);
}

extern "C" void kernel_launch(void* const* d_in, const int* in_sizes, int n_in,
                              void* d_out, int out_size) {
    const float* lb = (const float*)d_in[0];   // log_belief  (4,4,128,128)
    const float* lk = (const float*)d_in[1];   // log_kernel  (4,4,100,128,128)
    float* out = (float*)d_out;                // (4,4,128,128)

    const int blocks = PN * PCOUT * (PH / 2);  // 1024 blocks of 256 threads
    propagate_belief_kernel<<<blocks, 256>>>(lb, lk, out);
}